// round 1
// baseline (speedup 1.0000x reference)
#include <cuda_runtime.h>

// Problem constants
#define B_  32
#define M_  8192
#define Q_  64
#define D_  128

#define S_CHUNKS 16
#define CHUNK    (M_ / S_CHUNKS)   // 512 m per block
#define MT       128               // m-tile
#define NTILES   (CHUNK / MT)      // 4
#define THREADS  256

// Shared memory layout (floats)
//  a_s   : 128*128      = 16384   (story_a tile, then reused for story_c tile)
//  u_s   : 64*128       = 8192    (u, XOR-swizzled granules)
//  s_buf : 128*65       = 8320    (scores, padded rows, conflict-free softmax)
//  p_s   : 64*128       = 8192    (softmaxed p, transposed+swizzled)
#define A_OFF   0
#define U_OFF   16384
#define S_OFF   (16384 + 8192)
#define P_OFF   (16384 + 8192 + 8320)
#define SMEM_FLOATS (16384 + 8192 + 8320 + 8192)
#define SMEM_BYTES  (SMEM_FLOATS * 4)

// ---------------------------------------------------------------------------
// Kernel A: out[b,q,:] = u[b,q,:] @ H   (initializes the whole output)
// ---------------------------------------------------------------------------
__global__ __launch_bounds__(128) void uh_kernel(
    const float* __restrict__ u, const float* __restrict__ H,
    float* __restrict__ out)
{
    __shared__ float us[D_];
    int bq  = blockIdx.x;        // 0 .. B*Q-1
    int tid = threadIdx.x;       // d index
    us[tid] = u[(size_t)bq * D_ + tid];
    __syncthreads();
    float acc = 0.f;
#pragma unroll 16
    for (int e = 0; e < D_; ++e)
        acc += us[e] * H[e * D_ + tid];
    out[(size_t)bq * D_ + tid] = acc;
}

// ---------------------------------------------------------------------------
// Kernel B: fused  scores -> softmax(axis=Q) -> p^T @ story_c, atomicAdd out
// ---------------------------------------------------------------------------
__global__ __launch_bounds__(THREADS, 1) void attn_kernel(
    const float* __restrict__ story_a, const float* __restrict__ u,
    const float* __restrict__ story_c, float* __restrict__ out)
{
    extern __shared__ float sm[];
    float*  a_s   = sm + A_OFF;
    float*  u_s   = sm + U_OFF;
    float*  s_buf = sm + S_OFF;
    float*  p_s   = sm + P_OFF;
    float4* a_s4  = reinterpret_cast<float4*>(a_s);
    float4* u_s4  = reinterpret_cast<float4*>(u_s);
    float4* p_s4  = reinterpret_cast<float4*>(p_s);

    const int tid   = threadIdx.x;
    const int b     = blockIdx.y;
    const int chunk = blockIdx.x;
    const int m_base = chunk * CHUNK;

    // ---- load u (64 x 128) into smem with XOR-swizzled 16B granules ----
    {
        const float4* ug4 = reinterpret_cast<const float4*>(u + (size_t)b * Q_ * D_);
        for (int gi = tid; gi < Q_ * D_ / 4; gi += THREADS) {
            int q  = gi >> 5;          // row (32 granules per row)
            int k4 = gi & 31;          // granule within row
            int g  = k4 ^ ((q >> 2) & 7);
            u_s4[q * 32 + g] = ug4[gi];
        }
    }

    // GEMM1 thread map: 8m x 4q per thread
    const int tq = tid & 15;   // q-group (16)
    const int tm = tid >> 4;   // m-group (16)
    // GEMM2 thread map: 4q x 8d per thread
    const int dg = tid & 15;   // d-group (16)
    const int qg = tid >> 4;   // q-group (16)

    // persistent output accumulators: c[4q][8d]
    float c[4][8];
#pragma unroll
    for (int j = 0; j < 4; ++j)
#pragma unroll
        for (int dd = 0; dd < 8; ++dd) c[j][dd] = 0.f;

    for (int t = 0; t < NTILES; ++t) {
        const int m0 = m_base + t * MT;

        __syncthreads();   // previous GEMM2 done with a_s / this covers u_s too
        // ---- stage story_a tile (128 x 128), natural layout ----
        {
            const float4* ag4 = reinterpret_cast<const float4*>(
                story_a + ((size_t)b * M_ + m0) * D_);
            for (int gi = tid; gi < MT * D_ / 4; gi += THREADS)
                a_s4[gi] = ag4[gi];
        }
        __syncthreads();

        // ---- GEMM1: s[m][q] = sum_d a[m][d] * u[q][d] ----
        float s[8][4];
#pragma unroll
        for (int i = 0; i < 8; ++i)
#pragma unroll
            for (int j = 0; j < 4; ++j) s[i][j] = 0.f;

#pragma unroll 4
        for (int k4 = 0; k4 < 32; ++k4) {
            float4 uv[4];
#pragma unroll
            for (int j = 0; j < 4; ++j) {
                int q = tq * 4 + j;
                uv[j] = u_s4[q * 32 + (k4 ^ (tq & 7))];
            }
#pragma unroll
            for (int i = 0; i < 8; ++i) {
                float4 av = a_s4[(tm * 8 + i) * 32 + k4];
#pragma unroll
                for (int j = 0; j < 4; ++j) {
                    s[i][j] += av.x * uv[j].x;
                    s[i][j] += av.y * uv[j].y;
                    s[i][j] += av.z * uv[j].z;
                    s[i][j] += av.w * uv[j].w;
                }
            }
        }

        // ---- spill scores to smem (row len 65 -> conflict-free softmax) ----
#pragma unroll
        for (int i = 0; i < 8; ++i)
#pragma unroll
            for (int j = 0; j < 4; ++j)
                s_buf[(tm * 8 + i) * 65 + tq * 4 + j] = s[i][j];
        __syncthreads();

        // ---- softmax over Q per m-row; write p transposed+swizzled ----
        if (tid < MT) {
            float* row = s_buf + tid * 65;
            float mx = -1e30f;
#pragma unroll 8
            for (int q = 0; q < Q_; ++q) mx = fmaxf(mx, row[q]);
            float sum = 0.f;
#pragma unroll 8
            for (int q = 0; q < Q_; ++q) {
                float ex = __expf(row[q] - mx);
                sum += ex;
                row[q] = ex;
            }
            float inv = 1.f / sum;
            const int mloc = tid;
            const int mg   = mloc >> 2;
            const int mr   = mloc & 3;
#pragma unroll 8
            for (int q = 0; q < Q_; ++q) {
                int gc = mg ^ ((q >> 2) & 15);
                p_s[q * 128 + gc * 4 + mr] = row[q] * inv;
            }
        }
        __syncthreads();

        // ---- stage story_c tile over a_s ----
        {
            const float4* cg4 = reinterpret_cast<const float4*>(
                story_c + ((size_t)b * M_ + m0) * D_);
            for (int gi = tid; gi < MT * D_ / 4; gi += THREADS)
                a_s4[gi] = cg4[gi];
        }
        __syncthreads();

        // ---- GEMM2: c[q][d] += sum_m p[q][m] * sc[m][d] ----
#pragma unroll 4
        for (int k4 = 0; k4 < 32; ++k4) {
            float pj[4][4];
#pragma unroll
            for (int j = 0; j < 4; ++j) {
                int q = qg * 4 + j;
                float4 pv = p_s4[q * 32 + (k4 ^ (qg & 15))];
                pj[j][0] = pv.x; pj[j][1] = pv.y; pj[j][2] = pv.z; pj[j][3] = pv.w;
            }
#pragma unroll
            for (int kk = 0; kk < 4; ++kk) {
                int m = k4 * 4 + kk;
                float4 c0 = a_s4[m * 32 + dg * 2 + 0];
                float4 c1 = a_s4[m * 32 + dg * 2 + 1];
#pragma unroll
                for (int j = 0; j < 4; ++j) {
                    float p = pj[j][kk];
                    c[j][0] += p * c0.x; c[j][1] += p * c0.y;
                    c[j][2] += p * c0.z; c[j][3] += p * c0.w;
                    c[j][4] += p * c1.x; c[j][5] += p * c1.y;
                    c[j][6] += p * c1.z; c[j][7] += p * c1.w;
                }
            }
        }
    }

    // ---- accumulate partial c into global out ----
#pragma unroll
    for (int j = 0; j < 4; ++j) {
        int q = qg * 4 + j;
        float* orow = out + ((size_t)b * Q_ + q) * D_ + dg * 8;
#pragma unroll
        for (int dd = 0; dd < 8; ++dd)
            atomicAdd(orow + dd, c[j][dd]);
    }
}

// ---------------------------------------------------------------------------
extern "C" void kernel_launch(void* const* d_in, const int* in_sizes, int n_in,
                              void* d_out, int out_size)
{
    (void)in_sizes; (void)n_in; (void)out_size;
    const float* story_a = (const float*)d_in[0];
    const float* u       = (const float*)d_in[1];
    const float* story_c = (const float*)d_in[2];
    const float* H       = (const float*)d_in[3];
    float* out = (float*)d_out;

    // 1) out = u @ H (initializes every output element)
    uh_kernel<<<B_ * Q_, 128>>>(u, H, out);

    // 2) fused attention accumulate
    cudaFuncSetAttribute(attn_kernel,
                         cudaFuncAttributeMaxDynamicSharedMemorySize, SMEM_BYTES);
    dim3 grid(S_CHUNKS, B_);
    attn_kernel<<<grid, THREADS, SMEM_BYTES>>>(story_a, u, story_c, out);
}